// round 11
// baseline (speedup 1.0000x reference)
#include <cuda_runtime.h>
#include <cuda_fp16.h>
#include <math_constants.h>
#include <cstdint>
#include <cstddef>

// ---------------------------------------------------------------------------
// Problem constants
// ---------------------------------------------------------------------------
#define D_MODEL 768
#define N_HEADS 12
#define D_HEAD  64
#define D_FF    3072
#define B_SZ    4
#define T_SEQ   2048
#define NTOK    (B_SZ * T_SEQ)      // 8192
#define D_QKV   (3 * D_MODEL)       // 2304
#define LN_EPS  1e-5f

#define W_QKV_N   (D_MODEL * D_QKV)
#define W_AO_N    (D_MODEL * D_MODEL)
#define W_FF1_N   (D_MODEL * D_FF)
#define W_FF2_N   (D_FF * D_MODEL)
#define W_TOTAL_N (W_QKV_N + W_AO_N + W_FF1_N + W_FF2_N)

// ---------------------------------------------------------------------------
// Scratch (device globals)
// ---------------------------------------------------------------------------
__device__ __half  g_h   [NTOK * D_MODEL];
__device__ __half  g_qkv [NTOK * D_QKV];
__device__ __half  g_attn[NTOK * D_MODEL];
__device__ float   g_x1  [NTOK * D_MODEL];
__device__ __half  g_mid [NTOK * D_FF];
__device__ __half  g_w   [W_TOTAL_N];

// ---------------------------------------------------------------------------
// weight conversion fp32 -> fp16 (single launch)
// ---------------------------------------------------------------------------
__global__ __launch_bounds__(256) void round_all_kernel(
    const float* __restrict__ w0, const float* __restrict__ w1,
    const float* __restrict__ w2, const float* __restrict__ w3,
    __half* __restrict__ dst)
{
    int i = (blockIdx.x * blockDim.x + threadIdx.x) * 4;
    if (i >= W_TOTAL_N) return;
    const float* src;
    int off;
    if (i < W_QKV_N)                        { src = w0; off = 0; }
    else if (i < W_QKV_N + W_AO_N)          { src = w1; off = W_QKV_N; }
    else if (i < W_QKV_N + W_AO_N + W_FF1_N){ src = w2; off = W_QKV_N + W_AO_N; }
    else                                    { src = w3; off = W_QKV_N + W_AO_N + W_FF1_N; }
    float4 v = *(const float4*)(src + (i - off));
    __half2 h0 = __floats2half2_rn(v.x, v.y);
    __half2 h1 = __floats2half2_rn(v.z, v.w);
    uint2 packed = make_uint2(*(uint32_t*)&h0, *(uint32_t*)&h1);
    *(uint2*)(dst + i) = packed;
}

// ---------------------------------------------------------------------------
// LayerNorm: one warp per token; fp16 output
// ---------------------------------------------------------------------------
__global__ __launch_bounds__(256) void ln_kernel(
    const float* __restrict__ x, const float* __restrict__ g,
    const float* __restrict__ b, __half* __restrict__ out)
{
    int warp = (blockIdx.x * blockDim.x + threadIdx.x) >> 5;
    int lane = threadIdx.x & 31;
    if (warp >= NTOK) return;
    const float* xr = x + (size_t)warp * D_MODEL;
    float v[24];
    float s = 0.f;
#pragma unroll
    for (int i = 0; i < 24; i++) { v[i] = xr[lane + 32 * i]; s += v[i]; }
#pragma unroll
    for (int off = 16; off > 0; off >>= 1) s += __shfl_xor_sync(0xffffffffu, s, off);
    float mu = s * (1.f / D_MODEL);
    float sq = 0.f;
#pragma unroll
    for (int i = 0; i < 24; i++) { float d = v[i] - mu; sq += d * d; }
#pragma unroll
    for (int off = 16; off > 0; off >>= 1) sq += __shfl_xor_sync(0xffffffffu, sq, off);
    float rs = rsqrtf(sq * (1.f / D_MODEL) + LN_EPS);
    __half* orow = out + (size_t)warp * D_MODEL;
#pragma unroll
    for (int i = 0; i < 24; i++) {
        int c = lane + 32 * i;
        orow[c] = __float2half_rn((v[i] - mu) * rs * g[c] + b[c]);
    }
}

// ---------------------------------------------------------------------------
// GELU (tanh approx)
// ---------------------------------------------------------------------------
__device__ __forceinline__ float gelu_tanh(float x) {
    float x3 = x * x * x;
    float t = tanhf(0.7978845608028654f * (x + 0.044715f * x3));
    return 0.5f * x * (1.f + t);
}

// ---------------------------------------------------------------------------
// mma / ldmatrix helpers
// ---------------------------------------------------------------------------
__device__ __forceinline__ void mma_fp16(float c[4], const uint32_t a[4],
                                         const uint32_t b[2]) {
    asm volatile(
        "mma.sync.aligned.m16n8k16.row.col.f32.f16.f16.f32 "
        "{%0,%1,%2,%3}, {%4,%5,%6,%7}, {%8,%9}, {%0,%1,%2,%3};"
        : "+f"(c[0]), "+f"(c[1]), "+f"(c[2]), "+f"(c[3])
        : "r"(a[0]), "r"(a[1]), "r"(a[2]), "r"(a[3]), "r"(b[0]), "r"(b[1]));
}

__device__ __forceinline__ void mma_f16acc(uint32_t c[2], const uint32_t a[4],
                                           const uint32_t b[2]) {
    asm volatile(
        "mma.sync.aligned.m16n8k16.row.col.f16.f16.f16.f16 "
        "{%0,%1}, {%2,%3,%4,%5}, {%6,%7}, {%0,%1};"
        : "+r"(c[0]), "+r"(c[1])
        : "r"(a[0]), "r"(a[1]), "r"(a[2]), "r"(a[3]), "r"(b[0]), "r"(b[1]));
}

__device__ __forceinline__ __half2 h2exp2_(__half2 x) {
    uint32_t r, xi = *(uint32_t*)&x;
    asm("ex2.approx.f16x2 %0, %1;" : "=r"(r) : "r"(xi));
    return *(__half2*)&r;
}

__device__ __forceinline__ void ldsm_x4(uint32_t& r0, uint32_t& r1,
                                        uint32_t& r2, uint32_t& r3,
                                        const void* p) {
    uint32_t sa = (uint32_t)__cvta_generic_to_shared(p);
    asm volatile("ldmatrix.sync.aligned.m8n8.x4.shared.b16 {%0,%1,%2,%3}, [%4];"
                 : "=r"(r0), "=r"(r1), "=r"(r2), "=r"(r3) : "r"(sa));
}

__device__ __forceinline__ void ldsm_x4_t(uint32_t& r0, uint32_t& r1,
                                          uint32_t& r2, uint32_t& r3,
                                          const void* p) {
    uint32_t sa = (uint32_t)__cvta_generic_to_shared(p);
    asm volatile("ldmatrix.sync.aligned.m8n8.x4.trans.shared.b16 {%0,%1,%2,%3}, [%4];"
                 : "=r"(r0), "=r"(r1), "=r"(r2), "=r"(r3) : "r"(sa));
}

__device__ __forceinline__ void cp_async16(void* smem_dst, const void* gsrc) {
    uint32_t d = (uint32_t)__cvta_generic_to_shared(smem_dst);
    asm volatile("cp.async.ca.shared.global [%0], [%1], 16;\n" ::"r"(d), "l"(gsrc));
}

// ---------------------------------------------------------------------------
// fp16 tensor-core GEMM, 3-stage cp.async pipeline (validated, unchanged)
// ---------------------------------------------------------------------------
#define AH_STRIDE 40
#define BH_STRIDE 136
#define AH_HALFS (128 * AH_STRIDE)
#define BH_HALFS (32 * BH_STRIDE)
#define GEMM_SMEM_BYTES ((3 * AH_HALFS + 3 * BH_HALFS) * 2)   // 56832 B

__global__ __launch_bounds__(256, 2) void fp16_gemm_kernel(
    const __half* __restrict__ A, const __half* __restrict__ W,
    const float* __restrict__ bias, const float* __restrict__ resid,
    void* __restrict__ Cv, int M, int N, int K, int epi, int out_half)
{
    extern __shared__ __half smh[];
    __half* Asm = smh;
    __half* Bsm = smh + 3 * AH_HALFS;

    int tid = threadIdx.x;
    int lane = tid & 31;
    int warp = tid >> 5;
    int g = lane >> 2;
    int t = lane & 3;
    int m_w = (warp >> 2) * 64;
    int n_w = (warp & 3) * 32;

    int rowBase = blockIdx.y * 128;
    int colBase = blockIdx.x * 128;

    const __half* Ag = A + (size_t)rowBase * K;
    const __half* Wg = W + colBase;

    float acc[4][4][4];
#pragma unroll
    for (int mf = 0; mf < 4; mf++)
#pragma unroll
        for (int nf = 0; nf < 4; nf++)
#pragma unroll
            for (int i = 0; i < 4; i++) acc[mf][nf][i] = 0.f;

    int ntiles = K / 32;

    auto issue_copy = [&](int s, int kt) {
        __half* as = Asm + s * AH_HALFS;
        __half* bs = Bsm + s * BH_HALFS;
#pragma unroll
        for (int i = 0; i < 2; i++) {
            int id = tid + i * 256;
            int r = id >> 2;
            int c = (id & 3) * 8;
            cp_async16(as + r * AH_STRIDE + c, Ag + (size_t)r * K + kt + c);
        }
#pragma unroll
        for (int i = 0; i < 2; i++) {
            int id = tid + i * 256;
            int r = id >> 4;
            int c = (id & 15) * 8;
            cp_async16(bs + r * BH_STRIDE + c, Wg + (size_t)(kt + r) * N + c);
        }
        asm volatile("cp.async.commit_group;\n");
    };

    issue_copy(0, 0);
    issue_copy(1, 32);

    for (int kt = 0; kt < ntiles; kt++) {
        if (kt == ntiles - 1) {
            asm volatile("cp.async.wait_group 0;\n");
        } else {
            asm volatile("cp.async.wait_group 1;\n");
        }
        __syncthreads();
        if (kt + 2 < ntiles) issue_copy((kt + 2) % 3, (kt + 2) * 32);

        const __half* as = Asm + (kt % 3) * AH_HALFS;
        const __half* bs = Bsm + (kt % 3) * BH_HALFS;

#pragma unroll
        for (int ks = 0; ks < 2; ks++) {
            uint32_t af[4][4];
#pragma unroll
            for (int mf = 0; mf < 4; mf++) {
                const __half* ap = as + (m_w + mf * 16 + (lane & 15)) * AH_STRIDE
                                      + ks * 16 + (lane >> 4) * 8;
                ldsm_x4(af[mf][0], af[mf][1], af[mf][2], af[mf][3], ap);
            }
            uint32_t bfr[2][4];
#pragma unroll
            for (int nfp = 0; nfp < 2; nfp++) {
                const __half* bp = bs + (ks * 16 + (lane & 15)) * BH_STRIDE
                                      + n_w + nfp * 16 + (lane >> 4) * 8;
                ldsm_x4_t(bfr[nfp][0], bfr[nfp][1], bfr[nfp][2], bfr[nfp][3], bp);
            }
#pragma unroll
            for (int mf = 0; mf < 4; mf++)
#pragma unroll
                for (int nf = 0; nf < 4; nf++) {
                    int nfp = nf >> 1, pr = nf & 1;
                    uint32_t bb[2] = {bfr[nfp][2 * pr], bfr[nfp][2 * pr + 1]};
                    mma_fp16(acc[mf][nf], af[mf], bb);
                }
        }
    }

#pragma unroll
    for (int mf = 0; mf < 4; mf++) {
        int row0 = rowBase + m_w + mf * 16 + g;
        int row1 = row0 + 8;
#pragma unroll
        for (int nf = 0; nf < 4; nf++) {
            int col = colBase + n_w + nf * 8 + 2 * t;
            float2 bv = *(const float2*)&bias[col];
            float v00 = acc[mf][nf][0] + bv.x;
            float v01 = acc[mf][nf][1] + bv.y;
            float v10 = acc[mf][nf][2] + bv.x;
            float v11 = acc[mf][nf][3] + bv.y;
            if (epi == 1) {
                v00 = gelu_tanh(v00); v01 = gelu_tanh(v01);
                v10 = gelu_tanh(v10); v11 = gelu_tanh(v11);
            } else if (epi == 2) {
                float2 r0 = *(const float2*)&resid[(size_t)row0 * N + col];
                float2 r1 = *(const float2*)&resid[(size_t)row1 * N + col];
                v00 += r0.x; v01 += r0.y; v10 += r1.x; v11 += r1.y;
            }
            if (out_half) {
                __half* Ch = (__half*)Cv;
                __half2 p0 = __floats2half2_rn(v00, v01);
                __half2 p1 = __floats2half2_rn(v10, v11);
                *(uint32_t*)&Ch[(size_t)row0 * N + col] = *(uint32_t*)&p0;
                *(uint32_t*)&Ch[(size_t)row1 * N + col] = *(uint32_t*)&p1;
            } else {
                float* C = (float*)Cv;
                *(float2*)&C[(size_t)row0 * N + col] = make_float2(v00, v01);
                *(float2*)&C[(size_t)row1 * N + col] = make_float2(v10, v11);
            }
        }
    }
}

// ---------------------------------------------------------------------------
// Flash attention: f16-accumulate S AND PV MMAs (2x HMMA rate), exp2 f16x2
// softmax, per-iter f16 PV partials folded into fp32 O via FFMA (o*sc + p).
// BQ=128, 4 warps x 32 rows, BK=64, 2-stage KV pipeline (55KB smem).
// ---------------------------------------------------------------------------
#define FST 72
#define FQ_ELEMS (128 * FST)
#define FKV_ELEMS (64 * FST)
#define FLASHB_SMEM_BYTES ((FQ_ELEMS + 4 * FKV_ELEMS) * 2)   // 55296 B

__global__ __launch_bounds__(128, 2) void flash_fp16_kernel(
    const __half* __restrict__ qkv, __half* __restrict__ attn_out)
{
    extern __shared__ __align__(16) char smraw[];
    __half* Qs = (__half*)smraw;
    __half* Ks = Qs + FQ_ELEMS;        // 2 stages x 64 rows
    __half* Vs = Ks + 2 * FKV_ELEMS;   // 2 stages x 64 rows

    int qi = blockIdx.x, h = blockIdx.y, bz = blockIdx.z;
    int tid = threadIdx.x;
    int lane = tid & 31;
    int warp = tid >> 5;
    int g = lane >> 2, t = lane & 3;
    int m_w = warp * 32;

    size_t rowB = (size_t)bz * T_SEQ;
    const __half* Qg = qkv + (rowB + (size_t)qi * 128) * D_QKV + h * D_HEAD;
    const __half* Kg = qkv + rowB * D_QKV + D_MODEL     + h * D_HEAD;
    const __half* Vg = qkv + rowB * D_QKV + 2 * D_MODEL + h * D_HEAD;

    // stage Q
#pragma unroll
    for (int i = 0; i < 8; i++) {
        int id = tid + i * 128;
        int r = id >> 3, c = (id & 7) * 8;
        cp_async16(Qs + r * FST + c, Qg + (size_t)r * D_QKV + c);
    }
    asm volatile("cp.async.commit_group;\n");

    auto load_kv = [&](int s, int kt) {
        const __half* Kt_ = Kg + (size_t)kt * 64 * D_QKV;
        const __half* Vt_ = Vg + (size_t)kt * 64 * D_QKV;
        __half* ks_ = Ks + s * FKV_ELEMS;
        __half* vs_ = Vs + s * FKV_ELEMS;
#pragma unroll
        for (int i = 0; i < 4; i++) {
            int id = tid + i * 128;
            int r = id >> 3, c = (id & 7) * 8;
            cp_async16(ks_ + r * FST + c, Kt_ + (size_t)r * D_QKV + c);
            cp_async16(vs_ + r * FST + c, Vt_ + (size_t)r * D_QKV + c);
        }
        asm volatile("cp.async.commit_group;\n");
    };
    load_kv(0, 0);

    asm volatile("cp.async.wait_group 1;\n");   // Q ready
    __syncthreads();

    // Q a-fragments, scaled by 0.125 * log2(e)
    uint32_t qa[2][4][4];
    {
        __half2 sc2 = __float2half2_rn(0.18033688011111837f);
#pragma unroll
        for (int mf = 0; mf < 2; mf++) {
            const __half* q0 = Qs + (m_w + mf * 16 + g) * FST;
            const __half* q1 = q0 + 8 * FST;
#pragma unroll
            for (int kb = 0; kb < 4; kb++) {
                __half2 v;
                v = __hmul2(*(const __half2*)(q0 + kb * 16 + 2 * t), sc2);
                qa[mf][kb][0] = *(uint32_t*)&v;
                v = __hmul2(*(const __half2*)(q1 + kb * 16 + 2 * t), sc2);
                qa[mf][kb][1] = *(uint32_t*)&v;
                v = __hmul2(*(const __half2*)(q0 + kb * 16 + 2 * t + 8), sc2);
                qa[mf][kb][2] = *(uint32_t*)&v;
                v = __hmul2(*(const __half2*)(q1 + kb * 16 + 2 * t + 8), sc2);
                qa[mf][kb][3] = *(uint32_t*)&v;
            }
        }
    }

    float o[2][8][4];
    float m[2][2], l[2][2];
#pragma unroll
    for (int mf = 0; mf < 2; mf++) {
#pragma unroll
        for (int nf = 0; nf < 8; nf++)
#pragma unroll
            for (int i = 0; i < 4; i++) o[mf][nf][i] = 0.f;
        m[mf][0] = m[mf][1] = -CUDART_INF_F;
        l[mf][0] = l[mf][1] = 0.f;
    }

    const int NITER = T_SEQ / 64;   // 32
    for (int kt = 0; kt < NITER; kt++) {
        if (kt + 1 < NITER) {
            load_kv((kt + 1) & 1, kt + 1);
            asm volatile("cp.async.wait_group 1;\n");
        } else {
            asm volatile("cp.async.wait_group 0;\n");
        }
        __syncthreads();

        const __half* ks_ = Ks + (kt & 1) * FKV_ELEMS;
        const __half* vs_ = Vs + (kt & 1) * FKV_ELEMS;

        // ---- S' = (Q*0.125*log2e) @ K^T in f16-accumulate ----
        uint32_t sh[2][8][2];
#pragma unroll
        for (int nf = 0; nf < 8; nf++) {
            uint32_t b0[4], b1[4];
            const __half* kp = ks_ + (nf * 8 + (lane & 7)) * FST + (lane >> 3) * 8;
            ldsm_x4(b0[0], b0[1], b0[2], b0[3], kp);
            ldsm_x4(b1[0], b1[1], b1[2], b1[3], kp + 32);
#pragma unroll
            for (int mf = 0; mf < 2; mf++) {
                sh[mf][nf][0] = 0u; sh[mf][nf][1] = 0u;
                { uint32_t bb[2] = {b0[0], b0[1]}; mma_f16acc(sh[mf][nf], qa[mf][0], bb); }
                { uint32_t bb[2] = {b0[2], b0[3]}; mma_f16acc(sh[mf][nf], qa[mf][1], bb); }
                { uint32_t bb[2] = {b1[0], b1[1]}; mma_f16acc(sh[mf][nf], qa[mf][2], bb); }
                { uint32_t bb[2] = {b1[2], b1[3]}; mma_f16acc(sh[mf][nf], qa[mf][3], bb); }
            }
        }

        // ---- online softmax in exp2 domain (no O rescale here) ----
        float sc_[2][2];
#pragma unroll
        for (int mf = 0; mf < 2; mf++) {
            __half2 hm0 = *(__half2*)&sh[mf][0][0];
            __half2 hm1 = *(__half2*)&sh[mf][0][1];
#pragma unroll
            for (int nf = 1; nf < 8; nf++) {
                hm0 = __hmax2(hm0, *(__half2*)&sh[mf][nf][0]);
                hm1 = __hmax2(hm1, *(__half2*)&sh[mf][nf][1]);
            }
            float mx0 = fmaxf(__low2float(hm0), __high2float(hm0));
            float mx1 = fmaxf(__low2float(hm1), __high2float(hm1));
#pragma unroll
            for (int off = 1; off <= 2; off <<= 1) {
                mx0 = fmaxf(mx0, __shfl_xor_sync(0xffffffffu, mx0, off));
                mx1 = fmaxf(mx1, __shfl_xor_sync(0xffffffffu, mx1, off));
            }
            float mn0 = fmaxf(m[mf][0], mx0), mn1 = fmaxf(m[mf][1], mx1);
            sc_[mf][0] = exp2f(m[mf][0] - mn0);
            sc_[mf][1] = exp2f(m[mf][1] - mn1);
            m[mf][0] = mn0; m[mf][1] = mn1;

            __half2 mn0h = __float2half2_rn(mn0);
            __half2 mn1h = __float2half2_rn(mn1);
            float rs0 = 0.f, rs1 = 0.f;
#pragma unroll
            for (int nf = 0; nf < 8; nf++) {
                __half2 e0 = h2exp2_(__hsub2(*(__half2*)&sh[mf][nf][0], mn0h));
                __half2 e1 = h2exp2_(__hsub2(*(__half2*)&sh[mf][nf][1], mn1h));
                sh[mf][nf][0] = *(uint32_t*)&e0;   // P packed (A-frag ready)
                sh[mf][nf][1] = *(uint32_t*)&e1;
                float2 f0 = __half22float2(e0);
                float2 f1 = __half22float2(e1);
                rs0 += f0.x + f0.y;
                rs1 += f1.x + f1.y;
            }
#pragma unroll
            for (int off = 1; off <= 2; off <<= 1) {
                rs0 += __shfl_xor_sync(0xffffffffu, rs0, off);
                rs1 += __shfl_xor_sync(0xffffffffu, rs1, off);
            }
            l[mf][0] = l[mf][0] * sc_[mf][0] + rs0;
            l[mf][1] = l[mf][1] * sc_[mf][1] + rs1;
        }

        // ---- PV in f16-accumulate: fresh partials each iteration ----
        uint32_t op[2][8][2];
#pragma unroll
        for (int mf = 0; mf < 2; mf++)
#pragma unroll
            for (int nf = 0; nf < 8; nf++) { op[mf][nf][0] = 0u; op[mf][nf][1] = 0u; }

#pragma unroll
        for (int kb = 0; kb < 4; kb++) {
            const __half* vp = vs_ + (kb * 16 + (lane & 15)) * FST + (lane >> 4) * 8;
#pragma unroll
            for (int nfp = 0; nfp < 4; nfp++) {
                uint32_t v0, v1, v2, v3;
                ldsm_x4_t(v0, v1, v2, v3, vp + nfp * 16);
#pragma unroll
                for (int mf = 0; mf < 2; mf++) {
                    uint32_t a[4] = {sh[mf][2*kb][0], sh[mf][2*kb][1],
                                     sh[mf][2*kb+1][0], sh[mf][2*kb+1][1]};
                    { uint32_t bb[2] = {v0, v1}; mma_f16acc(op[mf][2*nfp],     a, bb); }
                    { uint32_t bb[2] = {v2, v3}; mma_f16acc(op[mf][2*nfp + 1], a, bb); }
                }
            }
        }

        // fold partials into fp32 O: o = o*sc + partial (FFMA)
#pragma unroll
        for (int mf = 0; mf < 2; mf++) {
            float s0 = sc_[mf][0], s1 = sc_[mf][1];
#pragma unroll
            for (int nf = 0; nf < 8; nf++) {
                float2 f0 = __half22float2(*(__half2*)&op[mf][nf][0]); // row g
                float2 f1 = __half22float2(*(__half2*)&op[mf][nf][1]); // row g+8
                o[mf][nf][0] = fmaf(o[mf][nf][0], s0, f0.x);
                o[mf][nf][1] = fmaf(o[mf][nf][1], s0, f0.y);
                o[mf][nf][2] = fmaf(o[mf][nf][2], s1, f1.x);
                o[mf][nf][3] = fmaf(o[mf][nf][3], s1, f1.y);
            }
        }
        __syncthreads();   // stage reuse barrier
    }

    // ---- epilogue: O / l -> fp16 attn ----
#pragma unroll
    for (int mf = 0; mf < 2; mf++) {
        float i0 = 1.f / l[mf][0], i1 = 1.f / l[mf][1];
        size_t tok0 = rowB + (size_t)qi * 128 + m_w + mf * 16 + g;
        __half* out0 = attn_out + tok0 * D_MODEL + h * D_HEAD;
        __half* out1 = out0 + 8 * (size_t)D_MODEL;
#pragma unroll
        for (int nf = 0; nf < 8; nf++) {
            __half2 p0 = __floats2half2_rn(o[mf][nf][0] * i0, o[mf][nf][1] * i0);
            __half2 p1 = __floats2half2_rn(o[mf][nf][2] * i1, o[mf][nf][3] * i1);
            *(uint32_t*)(out0 + nf * 8 + 2 * t) = *(uint32_t*)&p0;
            *(uint32_t*)(out1 + nf * 8 + 2 * t) = *(uint32_t*)&p1;
        }
    }
}

// ---------------------------------------------------------------------------
// Launch
// ---------------------------------------------------------------------------
extern "C" void kernel_launch(void* const* d_in, const int* in_sizes, int n_in,
                              void* d_out, int out_size)
{
    const float* x          = (const float*)d_in[0];
    const float* ln1_g      = (const float*)d_in[1];
    const float* ln1_b      = (const float*)d_in[2];
    const float* qkv_w      = (const float*)d_in[3];
    const float* qkv_b      = (const float*)d_in[4];
    const float* attn_out_w = (const float*)d_in[5];
    const float* attn_out_b = (const float*)d_in[6];
    const float* ln2_g      = (const float*)d_in[7];
    const float* ln2_b      = (const float*)d_in[8];
    const float* ff1_w      = (const float*)d_in[9];
    const float* ff1_b      = (const float*)d_in[10];
    const float* ff2_w      = (const float*)d_in[11];
    const float* ff2_b      = (const float*)d_in[12];
    float* out = (float*)d_out;

    void *p_h, *p_qkv, *p_attn, *p_x1, *p_mid, *p_w;
    cudaGetSymbolAddress(&p_h,    g_h);
    cudaGetSymbolAddress(&p_qkv,  g_qkv);
    cudaGetSymbolAddress(&p_attn, g_attn);
    cudaGetSymbolAddress(&p_x1,   g_x1);
    cudaGetSymbolAddress(&p_mid,  g_mid);
    cudaGetSymbolAddress(&p_w,    g_w);
    __half* h    = (__half*)p_h;
    __half* qkv  = (__half*)p_qkv;
    __half* attn = (__half*)p_attn;
    float*  x1   = (float*)p_x1;
    __half* mid  = (__half*)p_mid;
    __half* w_qkv = (__half*)p_w;
    __half* w_ao  = w_qkv + W_QKV_N;
    __half* w_ff1 = w_ao  + W_AO_N;
    __half* w_ff2 = w_ff1 + W_FF1_N;

    cudaFuncSetAttribute(flash_fp16_kernel,
                         cudaFuncAttributeMaxDynamicSharedMemorySize,
                         FLASHB_SMEM_BYTES);
    cudaFuncSetAttribute(fp16_gemm_kernel,
                         cudaFuncAttributeMaxDynamicSharedMemorySize,
                         GEMM_SMEM_BYTES);

    // 0. convert all weights to fp16
    round_all_kernel<<<(W_TOTAL_N / 4 + 255) / 256, 256>>>(
        qkv_w, attn_out_w, ff1_w, ff2_w, (__half*)p_w);

    // 1. h = LN1(x)
    ln_kernel<<<NTOK / 8, 256>>>(x, ln1_g, ln1_b, h);
    // 2. qkv = h @ qkv_w + qkv_b
    fp16_gemm_kernel<<<dim3(D_QKV / 128, NTOK / 128), 256, GEMM_SMEM_BYTES>>>(
        h, w_qkv, qkv_b, nullptr, qkv, NTOK, D_QKV, D_MODEL, 0, 1);
    // 3. attention
    flash_fp16_kernel<<<dim3(T_SEQ / 128, N_HEADS, B_SZ), 128, FLASHB_SMEM_BYTES>>>(
        qkv, attn);
    // 4. x1 = x + attn @ attn_out_w + attn_out_b
    fp16_gemm_kernel<<<dim3(D_MODEL / 128, NTOK / 128), 256, GEMM_SMEM_BYTES>>>(
        attn, w_ao, attn_out_b, x, x1, NTOK, D_MODEL, D_MODEL, 2, 0);
    // 5. h = LN2(x1)
    ln_kernel<<<NTOK / 8, 256>>>(x1, ln2_g, ln2_b, h);
    // 6. mid = gelu(h @ ff1_w + ff1_b)
    fp16_gemm_kernel<<<dim3(D_FF / 128, NTOK / 128), 256, GEMM_SMEM_BYTES>>>(
        h, w_ff1, ff1_b, nullptr, mid, NTOK, D_FF, D_MODEL, 1, 1);
    // 7. out = x1 + mid @ ff2_w + ff2_b
    fp16_gemm_kernel<<<dim3(D_MODEL / 128, NTOK / 128), 256, GEMM_SMEM_BYTES>>>(
        mid, w_ff2, ff2_b, x1, out, NTOK, D_MODEL, D_FF, 2, 0);
}

// round 12
// speedup vs baseline: 1.0213x; 1.0213x over previous
#include <cuda_runtime.h>
#include <cuda_fp16.h>
#include <math_constants.h>
#include <cstdint>
#include <cstddef>

// ---------------------------------------------------------------------------
// Problem constants
// ---------------------------------------------------------------------------
#define D_MODEL 768
#define N_HEADS 12
#define D_HEAD  64
#define D_FF    3072
#define B_SZ    4
#define T_SEQ   2048
#define NTOK    (B_SZ * T_SEQ)      // 8192
#define D_QKV   (3 * D_MODEL)       // 2304
#define LN_EPS  1e-5f

#define W_QKV_N   (D_MODEL * D_QKV)
#define W_AO_N    (D_MODEL * D_MODEL)
#define W_FF1_N   (D_MODEL * D_FF)
#define W_FF2_N   (D_FF * D_MODEL)
#define W_TOTAL_N (W_QKV_N + W_AO_N + W_FF1_N + W_FF2_N)

// ---------------------------------------------------------------------------
// Scratch (device globals)
// ---------------------------------------------------------------------------
__device__ __half  g_h   [NTOK * D_MODEL];
__device__ __half  g_qkv [NTOK * D_QKV];
__device__ __half  g_attn[NTOK * D_MODEL];
__device__ float   g_x1  [NTOK * D_MODEL];
__device__ __half  g_mid [NTOK * D_FF];
__device__ __half  g_w   [W_TOTAL_N];

// ---------------------------------------------------------------------------
// weight conversion fp32 -> fp16 (single launch)
// ---------------------------------------------------------------------------
__global__ __launch_bounds__(256) void round_all_kernel(
    const float* __restrict__ w0, const float* __restrict__ w1,
    const float* __restrict__ w2, const float* __restrict__ w3,
    __half* __restrict__ dst)
{
    int i = (blockIdx.x * blockDim.x + threadIdx.x) * 4;
    if (i >= W_TOTAL_N) return;
    const float* src;
    int off;
    if (i < W_QKV_N)                        { src = w0; off = 0; }
    else if (i < W_QKV_N + W_AO_N)          { src = w1; off = W_QKV_N; }
    else if (i < W_QKV_N + W_AO_N + W_FF1_N){ src = w2; off = W_QKV_N + W_AO_N; }
    else                                    { src = w3; off = W_QKV_N + W_AO_N + W_FF1_N; }
    float4 v = *(const float4*)(src + (i - off));
    __half2 h0 = __floats2half2_rn(v.x, v.y);
    __half2 h1 = __floats2half2_rn(v.z, v.w);
    uint2 packed = make_uint2(*(uint32_t*)&h0, *(uint32_t*)&h1);
    *(uint2*)(dst + i) = packed;
}

// ---------------------------------------------------------------------------
// LayerNorm: one warp per token; fp16 output
// ---------------------------------------------------------------------------
__global__ __launch_bounds__(256) void ln_kernel(
    const float* __restrict__ x, const float* __restrict__ g,
    const float* __restrict__ b, __half* __restrict__ out)
{
    int warp = (blockIdx.x * blockDim.x + threadIdx.x) >> 5;
    int lane = threadIdx.x & 31;
    if (warp >= NTOK) return;
    const float* xr = x + (size_t)warp * D_MODEL;
    float v[24];
    float s = 0.f;
#pragma unroll
    for (int i = 0; i < 24; i++) { v[i] = xr[lane + 32 * i]; s += v[i]; }
#pragma unroll
    for (int off = 16; off > 0; off >>= 1) s += __shfl_xor_sync(0xffffffffu, s, off);
    float mu = s * (1.f / D_MODEL);
    float sq = 0.f;
#pragma unroll
    for (int i = 0; i < 24; i++) { float d = v[i] - mu; sq += d * d; }
#pragma unroll
    for (int off = 16; off > 0; off >>= 1) sq += __shfl_xor_sync(0xffffffffu, sq, off);
    float rs = rsqrtf(sq * (1.f / D_MODEL) + LN_EPS);
    __half* orow = out + (size_t)warp * D_MODEL;
#pragma unroll
    for (int i = 0; i < 24; i++) {
        int c = lane + 32 * i;
        orow[c] = __float2half_rn((v[i] - mu) * rs * g[c] + b[c]);
    }
}

// ---------------------------------------------------------------------------
// GELU (tanh approx)
// ---------------------------------------------------------------------------
__device__ __forceinline__ float gelu_tanh(float x) {
    float x3 = x * x * x;
    float t = tanhf(0.7978845608028654f * (x + 0.044715f * x3));
    return 0.5f * x * (1.f + t);
}

// ---------------------------------------------------------------------------
// mma / ldmatrix helpers
// ---------------------------------------------------------------------------
__device__ __forceinline__ void mma_fp16(float c[4], const uint32_t a[4],
                                         const uint32_t b[2]) {
    asm volatile(
        "mma.sync.aligned.m16n8k16.row.col.f32.f16.f16.f32 "
        "{%0,%1,%2,%3}, {%4,%5,%6,%7}, {%8,%9}, {%0,%1,%2,%3};"
        : "+f"(c[0]), "+f"(c[1]), "+f"(c[2]), "+f"(c[3])
        : "r"(a[0]), "r"(a[1]), "r"(a[2]), "r"(a[3]), "r"(b[0]), "r"(b[1]));
}

__device__ __forceinline__ void mma_f16acc(uint32_t c[2], const uint32_t a[4],
                                           const uint32_t b[2]) {
    asm volatile(
        "mma.sync.aligned.m16n8k16.row.col.f16.f16.f16.f16 "
        "{%0,%1}, {%2,%3,%4,%5}, {%6,%7}, {%0,%1};"
        : "+r"(c[0]), "+r"(c[1])
        : "r"(a[0]), "r"(a[1]), "r"(a[2]), "r"(a[3]), "r"(b[0]), "r"(b[1]));
}

__device__ __forceinline__ __half2 h2exp2_(__half2 x) {
    uint32_t r, xi = *(uint32_t*)&x;
    asm("ex2.approx.f16x2 %0, %1;" : "=r"(r) : "r"(xi));
    return *(__half2*)&r;
}

__device__ __forceinline__ void ldsm_x4(uint32_t& r0, uint32_t& r1,
                                        uint32_t& r2, uint32_t& r3,
                                        const void* p) {
    uint32_t sa = (uint32_t)__cvta_generic_to_shared(p);
    asm volatile("ldmatrix.sync.aligned.m8n8.x4.shared.b16 {%0,%1,%2,%3}, [%4];"
                 : "=r"(r0), "=r"(r1), "=r"(r2), "=r"(r3) : "r"(sa));
}

__device__ __forceinline__ void ldsm_x4_t(uint32_t& r0, uint32_t& r1,
                                          uint32_t& r2, uint32_t& r3,
                                          const void* p) {
    uint32_t sa = (uint32_t)__cvta_generic_to_shared(p);
    asm volatile("ldmatrix.sync.aligned.m8n8.x4.trans.shared.b16 {%0,%1,%2,%3}, [%4];"
                 : "=r"(r0), "=r"(r1), "=r"(r2), "=r"(r3) : "r"(sa));
}

__device__ __forceinline__ void cp_async16(void* smem_dst, const void* gsrc) {
    uint32_t d = (uint32_t)__cvta_generic_to_shared(smem_dst);
    asm volatile("cp.async.ca.shared.global [%0], [%1], 16;\n" ::"r"(d), "l"(gsrc));
}

// ---------------------------------------------------------------------------
// fp16 tensor-core GEMM, 3-stage cp.async pipeline (validated, unchanged)
// ---------------------------------------------------------------------------
#define AH_STRIDE 40
#define BH_STRIDE 136
#define AH_HALFS (128 * AH_STRIDE)
#define BH_HALFS (32 * BH_STRIDE)
#define GEMM_SMEM_BYTES ((3 * AH_HALFS + 3 * BH_HALFS) * 2)   // 56832 B

__global__ __launch_bounds__(256, 2) void fp16_gemm_kernel(
    const __half* __restrict__ A, const __half* __restrict__ W,
    const float* __restrict__ bias, const float* __restrict__ resid,
    void* __restrict__ Cv, int M, int N, int K, int epi, int out_half)
{
    extern __shared__ __half smh[];
    __half* Asm = smh;
    __half* Bsm = smh + 3 * AH_HALFS;

    int tid = threadIdx.x;
    int lane = tid & 31;
    int warp = tid >> 5;
    int g = lane >> 2;
    int t = lane & 3;
    int m_w = (warp >> 2) * 64;
    int n_w = (warp & 3) * 32;

    int rowBase = blockIdx.y * 128;
    int colBase = blockIdx.x * 128;

    const __half* Ag = A + (size_t)rowBase * K;
    const __half* Wg = W + colBase;

    float acc[4][4][4];
#pragma unroll
    for (int mf = 0; mf < 4; mf++)
#pragma unroll
        for (int nf = 0; nf < 4; nf++)
#pragma unroll
            for (int i = 0; i < 4; i++) acc[mf][nf][i] = 0.f;

    int ntiles = K / 32;

    auto issue_copy = [&](int s, int kt) {
        __half* as = Asm + s * AH_HALFS;
        __half* bs = Bsm + s * BH_HALFS;
#pragma unroll
        for (int i = 0; i < 2; i++) {
            int id = tid + i * 256;
            int r = id >> 2;
            int c = (id & 3) * 8;
            cp_async16(as + r * AH_STRIDE + c, Ag + (size_t)r * K + kt + c);
        }
#pragma unroll
        for (int i = 0; i < 2; i++) {
            int id = tid + i * 256;
            int r = id >> 4;
            int c = (id & 15) * 8;
            cp_async16(bs + r * BH_STRIDE + c, Wg + (size_t)(kt + r) * N + c);
        }
        asm volatile("cp.async.commit_group;\n");
    };

    issue_copy(0, 0);
    issue_copy(1, 32);

    for (int kt = 0; kt < ntiles; kt++) {
        if (kt == ntiles - 1) {
            asm volatile("cp.async.wait_group 0;\n");
        } else {
            asm volatile("cp.async.wait_group 1;\n");
        }
        __syncthreads();
        if (kt + 2 < ntiles) issue_copy((kt + 2) % 3, (kt + 2) * 32);

        const __half* as = Asm + (kt % 3) * AH_HALFS;
        const __half* bs = Bsm + (kt % 3) * BH_HALFS;

#pragma unroll
        for (int ks = 0; ks < 2; ks++) {
            uint32_t af[4][4];
#pragma unroll
            for (int mf = 0; mf < 4; mf++) {
                const __half* ap = as + (m_w + mf * 16 + (lane & 15)) * AH_STRIDE
                                      + ks * 16 + (lane >> 4) * 8;
                ldsm_x4(af[mf][0], af[mf][1], af[mf][2], af[mf][3], ap);
            }
            uint32_t bfr[2][4];
#pragma unroll
            for (int nfp = 0; nfp < 2; nfp++) {
                const __half* bp = bs + (ks * 16 + (lane & 15)) * BH_STRIDE
                                      + n_w + nfp * 16 + (lane >> 4) * 8;
                ldsm_x4_t(bfr[nfp][0], bfr[nfp][1], bfr[nfp][2], bfr[nfp][3], bp);
            }
#pragma unroll
            for (int mf = 0; mf < 4; mf++)
#pragma unroll
                for (int nf = 0; nf < 4; nf++) {
                    int nfp = nf >> 1, pr = nf & 1;
                    uint32_t bb[2] = {bfr[nfp][2 * pr], bfr[nfp][2 * pr + 1]};
                    mma_fp16(acc[mf][nf], af[mf], bb);
                }
        }
    }

#pragma unroll
    for (int mf = 0; mf < 4; mf++) {
        int row0 = rowBase + m_w + mf * 16 + g;
        int row1 = row0 + 8;
#pragma unroll
        for (int nf = 0; nf < 4; nf++) {
            int col = colBase + n_w + nf * 8 + 2 * t;
            float2 bv = *(const float2*)&bias[col];
            float v00 = acc[mf][nf][0] + bv.x;
            float v01 = acc[mf][nf][1] + bv.y;
            float v10 = acc[mf][nf][2] + bv.x;
            float v11 = acc[mf][nf][3] + bv.y;
            if (epi == 1) {
                v00 = gelu_tanh(v00); v01 = gelu_tanh(v01);
                v10 = gelu_tanh(v10); v11 = gelu_tanh(v11);
            } else if (epi == 2) {
                float2 r0 = *(const float2*)&resid[(size_t)row0 * N + col];
                float2 r1 = *(const float2*)&resid[(size_t)row1 * N + col];
                v00 += r0.x; v01 += r0.y; v10 += r1.x; v11 += r1.y;
            }
            if (out_half) {
                __half* Ch = (__half*)Cv;
                __half2 p0 = __floats2half2_rn(v00, v01);
                __half2 p1 = __floats2half2_rn(v10, v11);
                *(uint32_t*)&Ch[(size_t)row0 * N + col] = *(uint32_t*)&p0;
                *(uint32_t*)&Ch[(size_t)row1 * N + col] = *(uint32_t*)&p1;
            } else {
                float* C = (float*)Cv;
                *(float2*)&C[(size_t)row0 * N + col] = make_float2(v00, v01);
                *(float2*)&C[(size_t)row1 * N + col] = make_float2(v10, v11);
            }
        }
    }
}

// ---------------------------------------------------------------------------
// Flash attention: R9 math (f16-acc S, exp2 f16x2 softmax, f32-acc PV),
// BK=128: halves iteration count -> half the barriers/shuffle chains.
// BQ=128, 4 warps x 32 rows, 2-stage KV pipeline (90KB smem, 2 CTAs/SM).
// ---------------------------------------------------------------------------
#define FST 72
#define FQ_ELEMS (128 * FST)
#define FKV_ELEMS (128 * FST)
#define FLASHB_SMEM_BYTES ((FQ_ELEMS + 4 * FKV_ELEMS) * 2)   // 92160 B

__global__ __launch_bounds__(128, 2) void flash_fp16_kernel(
    const __half* __restrict__ qkv, __half* __restrict__ attn_out)
{
    extern __shared__ __align__(16) char smraw[];
    __half* Qs = (__half*)smraw;
    __half* Ks = Qs + FQ_ELEMS;        // 2 stages x 128 rows
    __half* Vs = Ks + 2 * FKV_ELEMS;   // 2 stages x 128 rows

    int qi = blockIdx.x, h = blockIdx.y, bz = blockIdx.z;
    int tid = threadIdx.x;
    int lane = tid & 31;
    int warp = tid >> 5;
    int g = lane >> 2, t = lane & 3;
    int m_w = warp * 32;

    size_t rowB = (size_t)bz * T_SEQ;
    const __half* Qg = qkv + (rowB + (size_t)qi * 128) * D_QKV + h * D_HEAD;
    const __half* Kg = qkv + rowB * D_QKV + D_MODEL     + h * D_HEAD;
    const __half* Vg = qkv + rowB * D_QKV + 2 * D_MODEL + h * D_HEAD;

    // stage Q: 128 rows x 64 cols
#pragma unroll
    for (int i = 0; i < 8; i++) {
        int id = tid + i * 128;
        int r = id >> 3, c = (id & 7) * 8;
        cp_async16(Qs + r * FST + c, Qg + (size_t)r * D_QKV + c);
    }
    asm volatile("cp.async.commit_group;\n");

    auto load_kv = [&](int s, int kt) {
        const __half* Kt_ = Kg + (size_t)kt * 128 * D_QKV;
        const __half* Vt_ = Vg + (size_t)kt * 128 * D_QKV;
        __half* ks_ = Ks + s * FKV_ELEMS;
        __half* vs_ = Vs + s * FKV_ELEMS;
#pragma unroll
        for (int i = 0; i < 8; i++) {
            int id = tid + i * 128;
            int r = id >> 3, c = (id & 7) * 8;
            cp_async16(ks_ + r * FST + c, Kt_ + (size_t)r * D_QKV + c);
            cp_async16(vs_ + r * FST + c, Vt_ + (size_t)r * D_QKV + c);
        }
        asm volatile("cp.async.commit_group;\n");
    };
    load_kv(0, 0);

    asm volatile("cp.async.wait_group 1;\n");   // Q ready
    __syncthreads();

    // Q a-fragments, scaled by 0.125 * log2(e)
    uint32_t qa[2][4][4];
    {
        __half2 sc2 = __float2half2_rn(0.18033688011111837f);
#pragma unroll
        for (int mf = 0; mf < 2; mf++) {
            const __half* q0 = Qs + (m_w + mf * 16 + g) * FST;
            const __half* q1 = q0 + 8 * FST;
#pragma unroll
            for (int kb = 0; kb < 4; kb++) {
                __half2 v;
                v = __hmul2(*(const __half2*)(q0 + kb * 16 + 2 * t), sc2);
                qa[mf][kb][0] = *(uint32_t*)&v;
                v = __hmul2(*(const __half2*)(q1 + kb * 16 + 2 * t), sc2);
                qa[mf][kb][1] = *(uint32_t*)&v;
                v = __hmul2(*(const __half2*)(q0 + kb * 16 + 2 * t + 8), sc2);
                qa[mf][kb][2] = *(uint32_t*)&v;
                v = __hmul2(*(const __half2*)(q1 + kb * 16 + 2 * t + 8), sc2);
                qa[mf][kb][3] = *(uint32_t*)&v;
            }
        }
    }

    float o[2][8][4];
    float m[2][2], l[2][2];
#pragma unroll
    for (int mf = 0; mf < 2; mf++) {
#pragma unroll
        for (int nf = 0; nf < 8; nf++)
#pragma unroll
            for (int i = 0; i < 4; i++) o[mf][nf][i] = 0.f;
        m[mf][0] = m[mf][1] = -CUDART_INF_F;
        l[mf][0] = l[mf][1] = 0.f;
    }

    const int NITER = T_SEQ / 128;   // 16
    for (int kt = 0; kt < NITER; kt++) {
        if (kt + 1 < NITER) {
            load_kv((kt + 1) & 1, kt + 1);
            asm volatile("cp.async.wait_group 1;\n");
        } else {
            asm volatile("cp.async.wait_group 0;\n");
        }
        __syncthreads();

        const __half* ks_ = Ks + (kt & 1) * FKV_ELEMS;
        const __half* vs_ = Vs + (kt & 1) * FKV_ELEMS;

        // ---- S' = (Q*0.125*log2e) @ K^T in f16-accumulate : 16 n-frags ----
        uint32_t sh[2][16][2];
#pragma unroll
        for (int nf = 0; nf < 16; nf++) {
            uint32_t b0[4], b1[4];
            const __half* kp = ks_ + (nf * 8 + (lane & 7)) * FST + (lane >> 3) * 8;
            ldsm_x4(b0[0], b0[1], b0[2], b0[3], kp);
            ldsm_x4(b1[0], b1[1], b1[2], b1[3], kp + 32);
#pragma unroll
            for (int mf = 0; mf < 2; mf++) {
                sh[mf][nf][0] = 0u; sh[mf][nf][1] = 0u;
                { uint32_t bb[2] = {b0[0], b0[1]}; mma_f16acc(sh[mf][nf], qa[mf][0], bb); }
                { uint32_t bb[2] = {b0[2], b0[3]}; mma_f16acc(sh[mf][nf], qa[mf][1], bb); }
                { uint32_t bb[2] = {b1[0], b1[1]}; mma_f16acc(sh[mf][nf], qa[mf][2], bb); }
                { uint32_t bb[2] = {b1[2], b1[3]}; mma_f16acc(sh[mf][nf], qa[mf][3], bb); }
            }
        }

        // ---- online softmax in exp2 domain ----
        float sc_[2][2];
#pragma unroll
        for (int mf = 0; mf < 2; mf++) {
            __half2 hm0 = *(__half2*)&sh[mf][0][0];
            __half2 hm1 = *(__half2*)&sh[mf][0][1];
#pragma unroll
            for (int nf = 1; nf < 16; nf++) {
                hm0 = __hmax2(hm0, *(__half2*)&sh[mf][nf][0]);
                hm1 = __hmax2(hm1, *(__half2*)&sh[mf][nf][1]);
            }
            float mx0 = fmaxf(__low2float(hm0), __high2float(hm0));
            float mx1 = fmaxf(__low2float(hm1), __high2float(hm1));
#pragma unroll
            for (int off = 1; off <= 2; off <<= 1) {
                mx0 = fmaxf(mx0, __shfl_xor_sync(0xffffffffu, mx0, off));
                mx1 = fmaxf(mx1, __shfl_xor_sync(0xffffffffu, mx1, off));
            }
            float mn0 = fmaxf(m[mf][0], mx0), mn1 = fmaxf(m[mf][1], mx1);
            sc_[mf][0] = exp2f(m[mf][0] - mn0);
            sc_[mf][1] = exp2f(m[mf][1] - mn1);
            m[mf][0] = mn0; m[mf][1] = mn1;

            __half2 mn0h = __float2half2_rn(mn0);
            __half2 mn1h = __float2half2_rn(mn1);
            float rs0 = 0.f, rs1 = 0.f;
#pragma unroll
            for (int nf = 0; nf < 16; nf++) {
                __half2 e0 = h2exp2_(__hsub2(*(__half2*)&sh[mf][nf][0], mn0h));
                __half2 e1 = h2exp2_(__hsub2(*(__half2*)&sh[mf][nf][1], mn1h));
                sh[mf][nf][0] = *(uint32_t*)&e0;   // P packed (A-frag ready)
                sh[mf][nf][1] = *(uint32_t*)&e1;
                float2 f0 = __half22float2(e0);
                float2 f1 = __half22float2(e1);
                rs0 += f0.x + f0.y;
                rs1 += f1.x + f1.y;
            }
#pragma unroll
            for (int off = 1; off <= 2; off <<= 1) {
                rs0 += __shfl_xor_sync(0xffffffffu, rs0, off);
                rs1 += __shfl_xor_sync(0xffffffffu, rs1, off);
            }
            l[mf][0] = l[mf][0] * sc_[mf][0] + rs0;
            l[mf][1] = l[mf][1] * sc_[mf][1] + rs1;
#pragma unroll
            for (int nf = 0; nf < 8; nf++) {
                o[mf][nf][0] *= sc_[mf][0]; o[mf][nf][1] *= sc_[mf][0];
                o[mf][nf][2] *= sc_[mf][1]; o[mf][nf][3] *= sc_[mf][1];
            }
        }

        // ---- O += P @ V (f32-accumulate) : 8 kb of 16 keys ----
#pragma unroll
        for (int kb = 0; kb < 8; kb++) {
            const __half* vp = vs_ + (kb * 16 + (lane & 15)) * FST + (lane >> 4) * 8;
#pragma unroll
            for (int nfp = 0; nfp < 4; nfp++) {
                uint32_t v0, v1, v2, v3;
                ldsm_x4_t(v0, v1, v2, v3, vp + nfp * 16);
#pragma unroll
                for (int mf = 0; mf < 2; mf++) {
                    uint32_t a[4] = {sh[mf][2*kb][0], sh[mf][2*kb][1],
                                     sh[mf][2*kb+1][0], sh[mf][2*kb+1][1]};
                    { uint32_t bb[2] = {v0, v1}; mma_fp16(o[mf][2*nfp],     a, bb); }
                    { uint32_t bb[2] = {v2, v3}; mma_fp16(o[mf][2*nfp + 1], a, bb); }
                }
            }
        }
        __syncthreads();   // stage reuse barrier
    }

    // ---- epilogue: O / l -> fp16 attn ----
#pragma unroll
    for (int mf = 0; mf < 2; mf++) {
        float i0 = 1.f / l[mf][0], i1 = 1.f / l[mf][1];
        size_t tok0 = rowB + (size_t)qi * 128 + m_w + mf * 16 + g;
        __half* out0 = attn_out + tok0 * D_MODEL + h * D_HEAD;
        __half* out1 = out0 + 8 * (size_t)D_MODEL;
#pragma unroll
        for (int nf = 0; nf < 8; nf++) {
            __half2 p0 = __floats2half2_rn(o[mf][nf][0] * i0, o[mf][nf][1] * i0);
            __half2 p1 = __floats2half2_rn(o[mf][nf][2] * i1, o[mf][nf][3] * i1);
            *(uint32_t*)(out0 + nf * 8 + 2 * t) = *(uint32_t*)&p0;
            *(uint32_t*)(out1 + nf * 8 + 2 * t) = *(uint32_t*)&p1;
        }
    }
}

// ---------------------------------------------------------------------------
// Launch
// ---------------------------------------------------------------------------
extern "C" void kernel_launch(void* const* d_in, const int* in_sizes, int n_in,
                              void* d_out, int out_size)
{
    const float* x          = (const float*)d_in[0];
    const float* ln1_g      = (const float*)d_in[1];
    const float* ln1_b      = (const float*)d_in[2];
    const float* qkv_w      = (const float*)d_in[3];
    const float* qkv_b      = (const float*)d_in[4];
    const float* attn_out_w = (const float*)d_in[5];
    const float* attn_out_b = (const float*)d_in[6];
    const float* ln2_g      = (const float*)d_in[7];
    const float* ln2_b      = (const float*)d_in[8];
    const float* ff1_w      = (const float*)d_in[9];
    const float* ff1_b      = (const float*)d_in[10];
    const float* ff2_w      = (const float*)d_in[11];
    const float* ff2_b      = (const float*)d_in[12];
    float* out = (float*)d_out;

    void *p_h, *p_qkv, *p_attn, *p_x1, *p_mid, *p_w;
    cudaGetSymbolAddress(&p_h,    g_h);
    cudaGetSymbolAddress(&p_qkv,  g_qkv);
    cudaGetSymbolAddress(&p_attn, g_attn);
    cudaGetSymbolAddress(&p_x1,   g_x1);
    cudaGetSymbolAddress(&p_mid,  g_mid);
    cudaGetSymbolAddress(&p_w,    g_w);
    __half* h    = (__half*)p_h;
    __half* qkv  = (__half*)p_qkv;
    __half* attn = (__half*)p_attn;
    float*  x1   = (float*)p_x1;
    __half* mid  = (__half*)p_mid;
    __half* w_qkv = (__half*)p_w;
    __half* w_ao  = w_qkv + W_QKV_N;
    __half* w_ff1 = w_ao  + W_AO_N;
    __half* w_ff2 = w_ff1 + W_FF1_N;

    cudaFuncSetAttribute(flash_fp16_kernel,
                         cudaFuncAttributeMaxDynamicSharedMemorySize,
                         FLASHB_SMEM_BYTES);
    cudaFuncSetAttribute(fp16_gemm_kernel,
                         cudaFuncAttributeMaxDynamicSharedMemorySize,
                         GEMM_SMEM_BYTES);

    // 0. convert all weights to fp16
    round_all_kernel<<<(W_TOTAL_N / 4 + 255) / 256, 256>>>(
        qkv_w, attn_out_w, ff1_w, ff2_w, (__half*)p_w);

    // 1. h = LN1(x)
    ln_kernel<<<NTOK / 8, 256>>>(x, ln1_g, ln1_b, h);
    // 2. qkv = h @ qkv_w + qkv_b
    fp16_gemm_kernel<<<dim3(D_QKV / 128, NTOK / 128), 256, GEMM_SMEM_BYTES>>>(
        h, w_qkv, qkv_b, nullptr, qkv, NTOK, D_QKV, D_MODEL, 0, 1);
    // 3. attention (BK=128, 16 iters)
    flash_fp16_kernel<<<dim3(T_SEQ / 128, N_HEADS, B_SZ), 128, FLASHB_SMEM_BYTES>>>(
        qkv, attn);
    // 4. x1 = x + attn @ attn_out_w + attn_out_b
    fp16_gemm_kernel<<<dim3(D_MODEL / 128, NTOK / 128), 256, GEMM_SMEM_BYTES>>>(
        attn, w_ao, attn_out_b, x, x1, NTOK, D_MODEL, D_MODEL, 2, 0);
    // 5. h = LN2(x1)
    ln_kernel<<<NTOK / 8, 256>>>(x1, ln2_g, ln2_b, h);
    // 6. mid = gelu(h @ ff1_w + ff1_b)
    fp16_gemm_kernel<<<dim3(D_FF / 128, NTOK / 128), 256, GEMM_SMEM_BYTES>>>(
        h, w_ff1, ff1_b, nullptr, mid, NTOK, D_FF, D_MODEL, 1, 1);
    // 7. out = x1 + mid @ ff2_w + ff2_b
    fp16_gemm_kernel<<<dim3(D_MODEL / 128, NTOK / 128), 256, GEMM_SMEM_BYTES>>>(
        mid, w_ff2, ff2_b, x1, out, NTOK, D_MODEL, D_FF, 2, 0);
}

// round 13
// speedup vs baseline: 1.0384x; 1.0168x over previous
#include <cuda_runtime.h>
#include <cuda_fp16.h>
#include <math_constants.h>
#include <cstdint>
#include <cstddef>

// ---------------------------------------------------------------------------
// Problem constants
// ---------------------------------------------------------------------------
#define D_MODEL 768
#define N_HEADS 12
#define D_HEAD  64
#define D_FF    3072
#define B_SZ    4
#define T_SEQ   2048
#define NTOK    (B_SZ * T_SEQ)      // 8192
#define D_QKV   (3 * D_MODEL)       // 2304
#define LN_EPS  1e-5f

#define W_QKV_N   (D_MODEL * D_QKV)
#define W_AO_N    (D_MODEL * D_MODEL)
#define W_FF1_N   (D_MODEL * D_FF)
#define W_FF2_N   (D_FF * D_MODEL)
#define W_TOTAL_N (W_QKV_N + W_AO_N + W_FF1_N + W_FF2_N)

// ---------------------------------------------------------------------------
// Scratch (device globals)
// ---------------------------------------------------------------------------
__device__ __half  g_h   [NTOK * D_MODEL];
__device__ __half  g_qkv [NTOK * D_QKV];
__device__ __half  g_attn[NTOK * D_MODEL];
__device__ float   g_x1  [NTOK * D_MODEL];
__device__ __half  g_mid [NTOK * D_FF];
__device__ __half  g_w   [W_TOTAL_N];

// ---------------------------------------------------------------------------
// PDL helpers
// ---------------------------------------------------------------------------
__device__ __forceinline__ void pdl_wait() {
    asm volatile("griddepcontrol.wait;" ::: "memory");
}
__device__ __forceinline__ void pdl_launch_dependents() {
    asm volatile("griddepcontrol.launch_dependents;" ::: "memory");
}

// ---------------------------------------------------------------------------
// weight conversion fp32 -> fp16 (single launch; first in chain, no wait)
// ---------------------------------------------------------------------------
__global__ __launch_bounds__(256) void round_all_kernel(
    const float* __restrict__ w0, const float* __restrict__ w1,
    const float* __restrict__ w2, const float* __restrict__ w3,
    __half* __restrict__ dst)
{
    int i = (blockIdx.x * blockDim.x + threadIdx.x) * 4;
    if (i >= W_TOTAL_N) return;
    const float* src;
    int off;
    if (i < W_QKV_N)                        { src = w0; off = 0; }
    else if (i < W_QKV_N + W_AO_N)          { src = w1; off = W_QKV_N; }
    else if (i < W_QKV_N + W_AO_N + W_FF1_N){ src = w2; off = W_QKV_N + W_AO_N; }
    else                                    { src = w3; off = W_QKV_N + W_AO_N + W_FF1_N; }
    float4 v = *(const float4*)(src + (i - off));
    pdl_launch_dependents();
    __half2 h0 = __floats2half2_rn(v.x, v.y);
    __half2 h1 = __floats2half2_rn(v.z, v.w);
    uint2 packed = make_uint2(*(uint32_t*)&h0, *(uint32_t*)&h1);
    *(uint2*)(dst + i) = packed;
}

// ---------------------------------------------------------------------------
// LayerNorm: one warp per token; vectorized float4 loads, fp16 output
// ---------------------------------------------------------------------------
__global__ __launch_bounds__(256) void ln_kernel(
    const float* __restrict__ x, const float* __restrict__ g,
    const float* __restrict__ b, __half* __restrict__ out)
{
    pdl_wait();
    int warp = (blockIdx.x * blockDim.x + threadIdx.x) >> 5;
    int lane = threadIdx.x & 31;
    if (warp >= NTOK) return;
    const float* xr = x + (size_t)warp * D_MODEL;
    float4 v[6];
    float s = 0.f;
#pragma unroll
    for (int i = 0; i < 6; i++) {
        v[i] = *(const float4*)(xr + lane * 4 + i * 128);
        s += v[i].x + v[i].y + v[i].z + v[i].w;
    }
#pragma unroll
    for (int off = 16; off > 0; off >>= 1) s += __shfl_xor_sync(0xffffffffu, s, off);
    float mu = s * (1.f / D_MODEL);
    float sq = 0.f;
#pragma unroll
    for (int i = 0; i < 6; i++) {
        float d0 = v[i].x - mu, d1 = v[i].y - mu, d2 = v[i].z - mu, d3 = v[i].w - mu;
        sq += d0 * d0 + d1 * d1 + d2 * d2 + d3 * d3;
    }
#pragma unroll
    for (int off = 16; off > 0; off >>= 1) sq += __shfl_xor_sync(0xffffffffu, sq, off);
    float rs = rsqrtf(sq * (1.f / D_MODEL) + LN_EPS);
    pdl_launch_dependents();
    __half* orow = out + (size_t)warp * D_MODEL;
#pragma unroll
    for (int i = 0; i < 6; i++) {
        int c = lane * 4 + i * 128;
        float4 gv = *(const float4*)(g + c);
        float4 bv = *(const float4*)(b + c);
        __half2 p0 = __floats2half2_rn((v[i].x - mu) * rs * gv.x + bv.x,
                                       (v[i].y - mu) * rs * gv.y + bv.y);
        __half2 p1 = __floats2half2_rn((v[i].z - mu) * rs * gv.z + bv.z,
                                       (v[i].w - mu) * rs * gv.w + bv.w);
        *(uint2*)(orow + c) = make_uint2(*(uint32_t*)&p0, *(uint32_t*)&p1);
    }
}

// ---------------------------------------------------------------------------
// GELU (tanh approx)
// ---------------------------------------------------------------------------
__device__ __forceinline__ float gelu_tanh(float x) {
    float x3 = x * x * x;
    float t = tanhf(0.7978845608028654f * (x + 0.044715f * x3));
    return 0.5f * x * (1.f + t);
}

// ---------------------------------------------------------------------------
// mma / ldmatrix helpers
// ---------------------------------------------------------------------------
__device__ __forceinline__ void mma_fp16(float c[4], const uint32_t a[4],
                                         const uint32_t b[2]) {
    asm volatile(
        "mma.sync.aligned.m16n8k16.row.col.f32.f16.f16.f32 "
        "{%0,%1,%2,%3}, {%4,%5,%6,%7}, {%8,%9}, {%0,%1,%2,%3};"
        : "+f"(c[0]), "+f"(c[1]), "+f"(c[2]), "+f"(c[3])
        : "r"(a[0]), "r"(a[1]), "r"(a[2]), "r"(a[3]), "r"(b[0]), "r"(b[1]));
}

__device__ __forceinline__ void mma_f16acc(uint32_t c[2], const uint32_t a[4],
                                           const uint32_t b[2]) {
    asm volatile(
        "mma.sync.aligned.m16n8k16.row.col.f16.f16.f16.f16 "
        "{%0,%1}, {%2,%3,%4,%5}, {%6,%7}, {%0,%1};"
        : "+r"(c[0]), "+r"(c[1])
        : "r"(a[0]), "r"(a[1]), "r"(a[2]), "r"(a[3]), "r"(b[0]), "r"(b[1]));
}

__device__ __forceinline__ __half2 h2exp2_(__half2 x) {
    uint32_t r, xi = *(uint32_t*)&x;
    asm("ex2.approx.f16x2 %0, %1;" : "=r"(r) : "r"(xi));
    return *(__half2*)&r;
}

__device__ __forceinline__ void ldsm_x4(uint32_t& r0, uint32_t& r1,
                                        uint32_t& r2, uint32_t& r3,
                                        const void* p) {
    uint32_t sa = (uint32_t)__cvta_generic_to_shared(p);
    asm volatile("ldmatrix.sync.aligned.m8n8.x4.shared.b16 {%0,%1,%2,%3}, [%4];"
                 : "=r"(r0), "=r"(r1), "=r"(r2), "=r"(r3) : "r"(sa));
}

__device__ __forceinline__ void ldsm_x4_t(uint32_t& r0, uint32_t& r1,
                                          uint32_t& r2, uint32_t& r3,
                                          const void* p) {
    uint32_t sa = (uint32_t)__cvta_generic_to_shared(p);
    asm volatile("ldmatrix.sync.aligned.m8n8.x4.trans.shared.b16 {%0,%1,%2,%3}, [%4];"
                 : "=r"(r0), "=r"(r1), "=r"(r2), "=r"(r3) : "r"(sa));
}

__device__ __forceinline__ void cp_async16(void* smem_dst, const void* gsrc) {
    uint32_t d = (uint32_t)__cvta_generic_to_shared(smem_dst);
    asm volatile("cp.async.ca.shared.global [%0], [%1], 16;\n" ::"r"(d), "l"(gsrc));
}

// ---------------------------------------------------------------------------
// fp16 tensor-core GEMM, 3-stage cp.async pipeline (validated R9 structure)
// ---------------------------------------------------------------------------
#define AH_STRIDE 40
#define BH_STRIDE 136
#define AH_HALFS (128 * AH_STRIDE)
#define BH_HALFS (32 * BH_STRIDE)
#define GEMM_SMEM_BYTES ((3 * AH_HALFS + 3 * BH_HALFS) * 2)   // 56832 B

__global__ __launch_bounds__(256, 2) void fp16_gemm_kernel(
    const __half* __restrict__ A, const __half* __restrict__ W,
    const float* __restrict__ bias, const float* __restrict__ resid,
    void* __restrict__ Cv, int M, int N, int K, int epi, int out_half)
{
    extern __shared__ __half smh[];
    __half* Asm = smh;
    __half* Bsm = smh + 3 * AH_HALFS;

    int tid = threadIdx.x;
    int lane = tid & 31;
    int warp = tid >> 5;
    int g = lane >> 2;
    int t = lane & 3;
    int m_w = (warp >> 2) * 64;
    int n_w = (warp & 3) * 32;

    int rowBase = blockIdx.y * 128;
    int colBase = blockIdx.x * 128;

    const __half* Ag = A + (size_t)rowBase * K;
    const __half* Wg = W + colBase;

    float acc[4][4][4];
#pragma unroll
    for (int mf = 0; mf < 4; mf++)
#pragma unroll
        for (int nf = 0; nf < 4; nf++)
#pragma unroll
            for (int i = 0; i < 4; i++) acc[mf][nf][i] = 0.f;

    int ntiles = K / 32;

    auto issue_copy = [&](int s, int kt) {
        __half* as = Asm + s * AH_HALFS;
        __half* bs = Bsm + s * BH_HALFS;
#pragma unroll
        for (int i = 0; i < 2; i++) {
            int id = tid + i * 256;
            int r = id >> 2;
            int c = (id & 3) * 8;
            cp_async16(as + r * AH_STRIDE + c, Ag + (size_t)r * K + kt + c);
        }
#pragma unroll
        for (int i = 0; i < 2; i++) {
            int id = tid + i * 256;
            int r = id >> 4;
            int c = (id & 15) * 8;
            cp_async16(bs + r * BH_STRIDE + c, Wg + (size_t)(kt + r) * N + c);
        }
        asm volatile("cp.async.commit_group;\n");
    };

    pdl_wait();   // producer outputs (A and rounded W) must be visible
    issue_copy(0, 0);
    issue_copy(1, 32);

    for (int kt = 0; kt < ntiles; kt++) {
        if (kt == ntiles - 1) {
            asm volatile("cp.async.wait_group 0;\n");
        } else {
            asm volatile("cp.async.wait_group 1;\n");
        }
        __syncthreads();
        if (kt + 2 < ntiles) issue_copy((kt + 2) % 3, (kt + 2) * 32);

        const __half* as = Asm + (kt % 3) * AH_HALFS;
        const __half* bs = Bsm + (kt % 3) * BH_HALFS;

#pragma unroll
        for (int ks = 0; ks < 2; ks++) {
            uint32_t af[4][4];
#pragma unroll
            for (int mf = 0; mf < 4; mf++) {
                const __half* ap = as + (m_w + mf * 16 + (lane & 15)) * AH_STRIDE
                                      + ks * 16 + (lane >> 4) * 8;
                ldsm_x4(af[mf][0], af[mf][1], af[mf][2], af[mf][3], ap);
            }
            uint32_t bfr[2][4];
#pragma unroll
            for (int nfp = 0; nfp < 2; nfp++) {
                const __half* bp = bs + (ks * 16 + (lane & 15)) * BH_STRIDE
                                      + n_w + nfp * 16 + (lane >> 4) * 8;
                ldsm_x4_t(bfr[nfp][0], bfr[nfp][1], bfr[nfp][2], bfr[nfp][3], bp);
            }
#pragma unroll
            for (int mf = 0; mf < 4; mf++)
#pragma unroll
                for (int nf = 0; nf < 4; nf++) {
                    int nfp = nf >> 1, pr = nf & 1;
                    uint32_t bb[2] = {bfr[nfp][2 * pr], bfr[nfp][2 * pr + 1]};
                    mma_fp16(acc[mf][nf], af[mf], bb);
                }
        }
    }

    pdl_launch_dependents();   // let next kernel start launching during epilogue

#pragma unroll
    for (int mf = 0; mf < 4; mf++) {
        int row0 = rowBase + m_w + mf * 16 + g;
        int row1 = row0 + 8;
#pragma unroll
        for (int nf = 0; nf < 4; nf++) {
            int col = colBase + n_w + nf * 8 + 2 * t;
            float2 bv = *(const float2*)&bias[col];
            float v00 = acc[mf][nf][0] + bv.x;
            float v01 = acc[mf][nf][1] + bv.y;
            float v10 = acc[mf][nf][2] + bv.x;
            float v11 = acc[mf][nf][3] + bv.y;
            if (epi == 1) {
                v00 = gelu_tanh(v00); v01 = gelu_tanh(v01);
                v10 = gelu_tanh(v10); v11 = gelu_tanh(v11);
            } else if (epi == 2) {
                float2 r0 = *(const float2*)&resid[(size_t)row0 * N + col];
                float2 r1 = *(const float2*)&resid[(size_t)row1 * N + col];
                v00 += r0.x; v01 += r0.y; v10 += r1.x; v11 += r1.y;
            }
            if (out_half) {
                __half* Ch = (__half*)Cv;
                __half2 p0 = __floats2half2_rn(v00, v01);
                __half2 p1 = __floats2half2_rn(v10, v11);
                *(uint32_t*)&Ch[(size_t)row0 * N + col] = *(uint32_t*)&p0;
                *(uint32_t*)&Ch[(size_t)row1 * N + col] = *(uint32_t*)&p1;
            } else {
                float* C = (float*)Cv;
                *(float2*)&C[(size_t)row0 * N + col] = make_float2(v00, v01);
                *(float2*)&C[(size_t)row1 * N + col] = make_float2(v10, v11);
            }
        }
    }
}

// ---------------------------------------------------------------------------
// Flash attention (R12-validated): f16-acc S, exp2 f16x2 softmax, f32-acc PV,
// BQ=128, 4 warps x 32 rows, BK=128, 2-stage KV pipeline (90KB, 2 CTAs/SM).
// ---------------------------------------------------------------------------
#define FST 72
#define FQ_ELEMS (128 * FST)
#define FKV_ELEMS (128 * FST)
#define FLASHB_SMEM_BYTES ((FQ_ELEMS + 4 * FKV_ELEMS) * 2)   // 92160 B

__global__ __launch_bounds__(128, 2) void flash_fp16_kernel(
    const __half* __restrict__ qkv, __half* __restrict__ attn_out)
{
    extern __shared__ __align__(16) char smraw[];
    __half* Qs = (__half*)smraw;
    __half* Ks = Qs + FQ_ELEMS;
    __half* Vs = Ks + 2 * FKV_ELEMS;

    int qi = blockIdx.x, h = blockIdx.y, bz = blockIdx.z;
    int tid = threadIdx.x;
    int lane = tid & 31;
    int warp = tid >> 5;
    int g = lane >> 2, t = lane & 3;
    int m_w = warp * 32;

    size_t rowB = (size_t)bz * T_SEQ;
    const __half* Qg = qkv + (rowB + (size_t)qi * 128) * D_QKV + h * D_HEAD;
    const __half* Kg = qkv + rowB * D_QKV + D_MODEL     + h * D_HEAD;
    const __half* Vg = qkv + rowB * D_QKV + 2 * D_MODEL + h * D_HEAD;

    pdl_wait();   // qkv must be complete

    // stage Q: 128 rows x 64 cols
#pragma unroll
    for (int i = 0; i < 8; i++) {
        int id = tid + i * 128;
        int r = id >> 3, c = (id & 7) * 8;
        cp_async16(Qs + r * FST + c, Qg + (size_t)r * D_QKV + c);
    }
    asm volatile("cp.async.commit_group;\n");

    auto load_kv = [&](int s, int kt) {
        const __half* Kt_ = Kg + (size_t)kt * 128 * D_QKV;
        const __half* Vt_ = Vg + (size_t)kt * 128 * D_QKV;
        __half* ks_ = Ks + s * FKV_ELEMS;
        __half* vs_ = Vs + s * FKV_ELEMS;
#pragma unroll
        for (int i = 0; i < 8; i++) {
            int id = tid + i * 128;
            int r = id >> 3, c = (id & 7) * 8;
            cp_async16(ks_ + r * FST + c, Kt_ + (size_t)r * D_QKV + c);
            cp_async16(vs_ + r * FST + c, Vt_ + (size_t)r * D_QKV + c);
        }
        asm volatile("cp.async.commit_group;\n");
    };
    load_kv(0, 0);

    asm volatile("cp.async.wait_group 1;\n");
    __syncthreads();

    // Q a-fragments, scaled by 0.125 * log2(e)
    uint32_t qa[2][4][4];
    {
        __half2 sc2 = __float2half2_rn(0.18033688011111837f);
#pragma unroll
        for (int mf = 0; mf < 2; mf++) {
            const __half* q0 = Qs + (m_w + mf * 16 + g) * FST;
            const __half* q1 = q0 + 8 * FST;
#pragma unroll
            for (int kb = 0; kb < 4; kb++) {
                __half2 v;
                v = __hmul2(*(const __half2*)(q0 + kb * 16 + 2 * t), sc2);
                qa[mf][kb][0] = *(uint32_t*)&v;
                v = __hmul2(*(const __half2*)(q1 + kb * 16 + 2 * t), sc2);
                qa[mf][kb][1] = *(uint32_t*)&v;
                v = __hmul2(*(const __half2*)(q0 + kb * 16 + 2 * t + 8), sc2);
                qa[mf][kb][2] = *(uint32_t*)&v;
                v = __hmul2(*(const __half2*)(q1 + kb * 16 + 2 * t + 8), sc2);
                qa[mf][kb][3] = *(uint32_t*)&v;
            }
        }
    }

    float o[2][8][4];
    float m[2][2], l[2][2];
#pragma unroll
    for (int mf = 0; mf < 2; mf++) {
#pragma unroll
        for (int nf = 0; nf < 8; nf++)
#pragma unroll
            for (int i = 0; i < 4; i++) o[mf][nf][i] = 0.f;
        m[mf][0] = m[mf][1] = -CUDART_INF_F;
        l[mf][0] = l[mf][1] = 0.f;
    }

    const int NITER = T_SEQ / 128;   // 16
    for (int kt = 0; kt < NITER; kt++) {
        if (kt + 1 < NITER) {
            load_kv((kt + 1) & 1, kt + 1);
            asm volatile("cp.async.wait_group 1;\n");
        } else {
            asm volatile("cp.async.wait_group 0;\n");
        }
        __syncthreads();

        const __half* ks_ = Ks + (kt & 1) * FKV_ELEMS;
        const __half* vs_ = Vs + (kt & 1) * FKV_ELEMS;

        // ---- S' in f16-accumulate : 16 n-frags ----
        uint32_t sh[2][16][2];
#pragma unroll
        for (int nf = 0; nf < 16; nf++) {
            uint32_t b0[4], b1[4];
            const __half* kp = ks_ + (nf * 8 + (lane & 7)) * FST + (lane >> 3) * 8;
            ldsm_x4(b0[0], b0[1], b0[2], b0[3], kp);
            ldsm_x4(b1[0], b1[1], b1[2], b1[3], kp + 32);
#pragma unroll
            for (int mf = 0; mf < 2; mf++) {
                sh[mf][nf][0] = 0u; sh[mf][nf][1] = 0u;
                { uint32_t bb[2] = {b0[0], b0[1]}; mma_f16acc(sh[mf][nf], qa[mf][0], bb); }
                { uint32_t bb[2] = {b0[2], b0[3]}; mma_f16acc(sh[mf][nf], qa[mf][1], bb); }
                { uint32_t bb[2] = {b1[0], b1[1]}; mma_f16acc(sh[mf][nf], qa[mf][2], bb); }
                { uint32_t bb[2] = {b1[2], b1[3]}; mma_f16acc(sh[mf][nf], qa[mf][3], bb); }
            }
        }

        // ---- online softmax in exp2 domain ----
        float sc_[2][2];
#pragma unroll
        for (int mf = 0; mf < 2; mf++) {
            __half2 hm0 = *(__half2*)&sh[mf][0][0];
            __half2 hm1 = *(__half2*)&sh[mf][0][1];
#pragma unroll
            for (int nf = 1; nf < 16; nf++) {
                hm0 = __hmax2(hm0, *(__half2*)&sh[mf][nf][0]);
                hm1 = __hmax2(hm1, *(__half2*)&sh[mf][nf][1]);
            }
            float mx0 = fmaxf(__low2float(hm0), __high2float(hm0));
            float mx1 = fmaxf(__low2float(hm1), __high2float(hm1));
#pragma unroll
            for (int off = 1; off <= 2; off <<= 1) {
                mx0 = fmaxf(mx0, __shfl_xor_sync(0xffffffffu, mx0, off));
                mx1 = fmaxf(mx1, __shfl_xor_sync(0xffffffffu, mx1, off));
            }
            float mn0 = fmaxf(m[mf][0], mx0), mn1 = fmaxf(m[mf][1], mx1);
            sc_[mf][0] = exp2f(m[mf][0] - mn0);
            sc_[mf][1] = exp2f(m[mf][1] - mn1);
            m[mf][0] = mn0; m[mf][1] = mn1;

            __half2 mn0h = __float2half2_rn(mn0);
            __half2 mn1h = __float2half2_rn(mn1);
            float rs0 = 0.f, rs1 = 0.f;
#pragma unroll
            for (int nf = 0; nf < 16; nf++) {
                __half2 e0 = h2exp2_(__hsub2(*(__half2*)&sh[mf][nf][0], mn0h));
                __half2 e1 = h2exp2_(__hsub2(*(__half2*)&sh[mf][nf][1], mn1h));
                sh[mf][nf][0] = *(uint32_t*)&e0;
                sh[mf][nf][1] = *(uint32_t*)&e1;
                float2 f0 = __half22float2(e0);
                float2 f1 = __half22float2(e1);
                rs0 += f0.x + f0.y;
                rs1 += f1.x + f1.y;
            }
#pragma unroll
            for (int off = 1; off <= 2; off <<= 1) {
                rs0 += __shfl_xor_sync(0xffffffffu, rs0, off);
                rs1 += __shfl_xor_sync(0xffffffffu, rs1, off);
            }
            l[mf][0] = l[mf][0] * sc_[mf][0] + rs0;
            l[mf][1] = l[mf][1] * sc_[mf][1] + rs1;
#pragma unroll
            for (int nf = 0; nf < 8; nf++) {
                o[mf][nf][0] *= sc_[mf][0]; o[mf][nf][1] *= sc_[mf][0];
                o[mf][nf][2] *= sc_[mf][1]; o[mf][nf][3] *= sc_[mf][1];
            }
        }

        // ---- O += P @ V (f32-accumulate) ----
#pragma unroll
        for (int kb = 0; kb < 8; kb++) {
            const __half* vp = vs_ + (kb * 16 + (lane & 15)) * FST + (lane >> 4) * 8;
#pragma unroll
            for (int nfp = 0; nfp < 4; nfp++) {
                uint32_t v0, v1, v2, v3;
                ldsm_x4_t(v0, v1, v2, v3, vp + nfp * 16);
#pragma unroll
                for (int mf = 0; mf < 2; mf++) {
                    uint32_t a[4] = {sh[mf][2*kb][0], sh[mf][2*kb][1],
                                     sh[mf][2*kb+1][0], sh[mf][2*kb+1][1]};
                    { uint32_t bb[2] = {v0, v1}; mma_fp16(o[mf][2*nfp],     a, bb); }
                    { uint32_t bb[2] = {v2, v3}; mma_fp16(o[mf][2*nfp + 1], a, bb); }
                }
            }
        }
        __syncthreads();
    }

    pdl_launch_dependents();

    // ---- epilogue: O / l -> fp16 attn ----
#pragma unroll
    for (int mf = 0; mf < 2; mf++) {
        float i0 = 1.f / l[mf][0], i1 = 1.f / l[mf][1];
        size_t tok0 = rowB + (size_t)qi * 128 + m_w + mf * 16 + g;
        __half* out0 = attn_out + tok0 * D_MODEL + h * D_HEAD;
        __half* out1 = out0 + 8 * (size_t)D_MODEL;
#pragma unroll
        for (int nf = 0; nf < 8; nf++) {
            __half2 p0 = __floats2half2_rn(o[mf][nf][0] * i0, o[mf][nf][1] * i0);
            __half2 p1 = __floats2half2_rn(o[mf][nf][2] * i1, o[mf][nf][3] * i1);
            *(uint32_t*)(out0 + nf * 8 + 2 * t) = *(uint32_t*)&p0;
            *(uint32_t*)(out1 + nf * 8 + 2 * t) = *(uint32_t*)&p1;
        }
    }
}

// ---------------------------------------------------------------------------
// Launch (PDL-chained)
// ---------------------------------------------------------------------------
static void launch_ex(const void* func, dim3 grid, dim3 block, size_t smem,
                      void** args, int pdl)
{
    cudaLaunchConfig_t cfg = {};
    cfg.gridDim = grid;
    cfg.blockDim = block;
    cfg.dynamicSmemBytes = smem;
    cfg.stream = 0;
    cudaLaunchAttribute attr[1];
    attr[0].id = cudaLaunchAttributeProgrammaticStreamSerialization;
    attr[0].val.programmaticStreamSerializationAllowed = 1;
    cfg.attrs = attr;
    cfg.numAttrs = pdl ? 1 : 0;
    cudaLaunchKernelExC(&cfg, func, args);
}

extern "C" void kernel_launch(void* const* d_in, const int* in_sizes, int n_in,
                              void* d_out, int out_size)
{
    const float* x          = (const float*)d_in[0];
    const float* ln1_g      = (const float*)d_in[1];
    const float* ln1_b      = (const float*)d_in[2];
    const float* qkv_w      = (const float*)d_in[3];
    const float* qkv_b      = (const float*)d_in[4];
    const float* attn_out_w = (const float*)d_in[5];
    const float* attn_out_b = (const float*)d_in[6];
    const float* ln2_g      = (const float*)d_in[7];
    const float* ln2_b      = (const float*)d_in[8];
    const float* ff1_w      = (const float*)d_in[9];
    const float* ff1_b      = (const float*)d_in[10];
    const float* ff2_w      = (const float*)d_in[11];
    const float* ff2_b      = (const float*)d_in[12];
    float* out = (float*)d_out;

    void *p_h, *p_qkv, *p_attn, *p_x1, *p_mid, *p_w;
    cudaGetSymbolAddress(&p_h,    g_h);
    cudaGetSymbolAddress(&p_qkv,  g_qkv);
    cudaGetSymbolAddress(&p_attn, g_attn);
    cudaGetSymbolAddress(&p_x1,   g_x1);
    cudaGetSymbolAddress(&p_mid,  g_mid);
    cudaGetSymbolAddress(&p_w,    g_w);
    __half* h    = (__half*)p_h;
    __half* qkv  = (__half*)p_qkv;
    __half* attn = (__half*)p_attn;
    float*  x1   = (float*)p_x1;
    __half* mid  = (__half*)p_mid;
    __half* w_qkv = (__half*)p_w;
    __half* w_ao  = w_qkv + W_QKV_N;
    __half* w_ff1 = w_ao  + W_AO_N;
    __half* w_ff2 = w_ff1 + W_FF1_N;

    cudaFuncSetAttribute(flash_fp16_kernel,
                         cudaFuncAttributeMaxDynamicSharedMemorySize,
                         FLASHB_SMEM_BYTES);
    cudaFuncSetAttribute(fp16_gemm_kernel,
                         cudaFuncAttributeMaxDynamicSharedMemorySize,
                         GEMM_SMEM_BYTES);

    // 0. convert all weights to fp16
    {
        void* args[] = {(void*)&qkv_w, (void*)&attn_out_w, (void*)&ff1_w,
                        (void*)&ff2_w, (void*)&p_w};
        launch_ex((const void*)round_all_kernel,
                  dim3((W_TOTAL_N / 4 + 255) / 256), dim3(256), 0, args, 0);
    }
    // 1. h = LN1(x)
    {
        void* args[] = {(void*)&x, (void*)&ln1_g, (void*)&ln1_b, (void*)&h};
        launch_ex((const void*)ln_kernel, dim3(NTOK / 8), dim3(256), 0, args, 1);
    }
    // 2. qkv = h @ qkv_w + qkv_b
    {
        const __half* A = h; const __half* W = w_qkv;
        const float* bias = qkv_b; const float* resid = nullptr;
        void* C = (void*)qkv;
        int M = NTOK, N = D_QKV, K = D_MODEL, epi = 0, oh = 1;
        void* args[] = {&A, &W, &bias, &resid, &C, &M, &N, &K, &epi, &oh};
        launch_ex((const void*)fp16_gemm_kernel,
                  dim3(D_QKV / 128, NTOK / 128), dim3(256), GEMM_SMEM_BYTES, args, 1);
    }
    // 3. attention
    {
        const __half* q = qkv; __half* a = attn;
        void* args[] = {&q, &a};
        launch_ex((const void*)flash_fp16_kernel,
                  dim3(T_SEQ / 128, N_HEADS, B_SZ), dim3(128), FLASHB_SMEM_BYTES, args, 1);
    }
    // 4. x1 = x + attn @ attn_out_w + attn_out_b
    {
        const __half* A = attn; const __half* W = w_ao;
        const float* bias = attn_out_b; const float* resid = x;
        void* C = (void*)x1;
        int M = NTOK, N = D_MODEL, K = D_MODEL, epi = 2, oh = 0;
        void* args[] = {&A, &W, &bias, &resid, &C, &M, &N, &K, &epi, &oh};
        launch_ex((const void*)fp16_gemm_kernel,
                  dim3(D_MODEL / 128, NTOK / 128), dim3(256), GEMM_SMEM_BYTES, args, 1);
    }
    // 5. h = LN2(x1)
    {
        const float* xin = x1;
        void* args[] = {(void*)&xin, (void*)&ln2_g, (void*)&ln2_b, (void*)&h};
        launch_ex((const void*)ln_kernel, dim3(NTOK / 8), dim3(256), 0, args, 1);
    }
    // 6. mid = gelu(h @ ff1_w + ff1_b)
    {
        const __half* A = h; const __half* W = w_ff1;
        const float* bias = ff1_b; const float* resid = nullptr;
        void* C = (void*)mid;
        int M = NTOK, N = D_FF, K = D_MODEL, epi = 1, oh = 1;
        void* args[] = {&A, &W, &bias, &resid, &C, &M, &N, &K, &epi, &oh};
        launch_ex((const void*)fp16_gemm_kernel,
                  dim3(D_FF / 128, NTOK / 128), dim3(256), GEMM_SMEM_BYTES, args, 1);
    }
    // 7. out = x1 + mid @ ff2_w + ff2_b
    {
        const __half* A = mid; const __half* W = w_ff2;
        const float* bias = ff2_b; const float* resid = x1;
        void* C = (void*)out;
        int M = NTOK, N = D_MODEL, K = D_FF, epi = 2, oh = 0;
        void* args[] = {&A, &W, &bias, &resid, &C, &M, &N, &K, &epi, &oh};
        launch_ex((const void*)fp16_gemm_kernel,
                  dim3(D_MODEL / 128, NTOK / 128), dim3(256), GEMM_SMEM_BYTES, args, 1);
    }
}